// round 1
// baseline (speedup 1.0000x reference)
#include <cuda_runtime.h>
#include <math.h>

#define HW   16384
#define B_   4

// ---------------- scratch (static device allocations are allowed) -------------
__device__ float g_xbuf0[B_*64*HW];
__device__ float g_xbuf1[B_*64*HW];
__device__ float g_off  [B_*18*HW];
__device__ float g_mask [B_*9*HW];
__device__ float g_xfin [B_*3*HW];
__device__ float g_ch   [B_*16*27];
__device__ float g_pool [B_*3];

__device__ __forceinline__ float sigm(float v){ return 1.f/(1.f+__expf(-v)); }

// ---------------- 1) ConvLSTM (h=c=0 => only 3 input channels, no f gate) -----
__global__ void lstm_kernel(const float* __restrict__ X, const float* __restrict__ w,
                            const float* __restrict__ bias,
                            float* __restrict__ hid, float* __restrict__ cell)
{
    int idx = blockIdx.x*256 + threadIdx.x;            // [b][k][y][x]
    int x = idx & 127, y = (idx >> 7) & 127, k = (idx >> 14) & 63, b = idx >> 20;
    float ai = bias[k], ao = bias[128+k], ag = bias[192+k];
    const float* Xb = X + b*3*HW;
    const float* wi = w + k*603;
    const float* wo = w + (128+k)*603;
    const float* wg = w + (192+k)*603;
    #pragma unroll
    for (int c = 0; c < 3; c++)
        #pragma unroll
        for (int dy = 0; dy < 3; dy++) {
            int yy = y + dy - 1;
            #pragma unroll
            for (int dx = 0; dx < 3; dx++) {
                int xx = x + dx - 1;
                float v = (yy >= 0 && yy < 128 && xx >= 0 && xx < 128)
                        ? Xb[c*HW + yy*128 + xx] : 0.f;
                int t = c*9 + dy*3 + dx;
                ai = fmaf(wi[t], v, ai);
                ao = fmaf(wo[t], v, ao);
                ag = fmaf(wg[t], v, ag);
            }
        }
    float cc = sigm(ai)*tanhf(ag);
    float hh = sigm(ao)*tanhf(cc);
    hid[idx]  = hh;
    cell[idx] = cc;
}

// ---------------- 2) generic 3x3 conv over concat(xin[64], lr[3]) -------------
// EPI 0: first C0 outputs raw -> out0 (offsets), rest 2*sigmoid -> out1 (mask)
// EPI 1: COUT outputs + bias  -> out0
template<int COUT, int C0, int EPI>
__global__ __launch_bounds__(256) void conv67_kernel(
    const float* __restrict__ xin, const float* __restrict__ lr,
    const float* __restrict__ w0, const float* __restrict__ b0,
    const float* __restrict__ w1, const float* __restrict__ b1,
    float* __restrict__ out0, float* __restrict__ out1)
{
    __shared__ float sT[16*10*34];         // channel-chunk input tile (with halo)
    __shared__ float sW[COUT*16*9];        // channel-chunk weights
    int tid = threadIdx.x;
    int tx = tid & 31, ty = tid >> 5;
    int b = blockIdx.z;
    int x = blockIdx.x*32 + tx, y = blockIdx.y*8 + ty;
    int gx0 = blockIdx.x*32 - 1, gy0 = blockIdx.y*8 - 1;

    float acc[COUT];
    #pragma unroll
    for (int o = 0; o < COUT; o++) acc[o] = 0.f;

    for (int c0 = 0; c0 < 67; c0 += 16) {
        int cnt = (67 - c0) < 16 ? (67 - c0) : 16;
        // stage input tile
        for (int i = tid; i < cnt*340; i += 256) {
            int c = i / 340, rem = i - c*340;
            int r = rem / 34, col = rem - r*34;
            int gy = gy0 + r, gx = gx0 + col;
            int cg = c0 + c;
            const float* src = (cg < 64) ? (xin + (b*64 + cg)*HW)
                                         : (lr  + (b*3 + (cg-64))*HW);
            sT[i] = (gy >= 0 && gy < 128 && gx >= 0 && gx < 128)
                  ? src[gy*128 + gx] : 0.f;
        }
        // stage weights
        int wtot = COUT*cnt*9;
        for (int i = tid; i < wtot; i += 256) {
            int o = i / (cnt*9), rem = i - o*(cnt*9);
            float wv = (o < C0) ? w0[o*603 + c0*9 + rem]
                                : w1[(o-C0)*603 + c0*9 + rem];
            sW[o*144 + rem] = wv;
        }
        __syncthreads();
        for (int c = 0; c < cnt; c++) {
            float win[9];
            #pragma unroll
            for (int r = 0; r < 3; r++)
                #pragma unroll
                for (int q = 0; q < 3; q++)
                    win[r*3+q] = sT[c*340 + (ty+r)*34 + (tx+q)];
            #pragma unroll
            for (int o = 0; o < COUT; o++) {
                #pragma unroll
                for (int t = 0; t < 9; t++)
                    acc[o] = fmaf(sW[o*144 + c*9 + t], win[t], acc[o]);
            }
        }
        __syncthreads();
    }

    int pix = y*128 + x;
    if (EPI == 0) {
        #pragma unroll
        for (int o = 0; o < C0; o++)
            out0[(b*C0 + o)*HW + pix] = acc[o] + b0[o];
        #pragma unroll
        for (int o = C0; o < COUT; o++) {
            float m = acc[o] + b1[o-C0];
            out1[(b*(COUT-C0) + (o-C0))*HW + pix] = 2.f*sigm(m);
        }
    } else {
        #pragma unroll
        for (int o = 0; o < COUT; o++)
            out0[(b*COUT + o)*HW + pix] = acc[o] + b0[o];
    }
}

// ---------------- 3) deformable gather + 64x603 GEMM per 32-pixel strip ------
// dynamic smem layout: sWt(float4[288]) | sV[603*33] | sW[64*68] | sIdx[288]
#define DSMEM_BYTES ((288*4 + 603*33 + 64*68 + 288) * 4)

__global__ __launch_bounds__(256) void deform_kernel(
    const float* __restrict__ xin, const float* __restrict__ lr,
    const float* __restrict__ wmain, const float* __restrict__ bias,
    float* __restrict__ out)
{
    extern __shared__ float smem[];
    float4* sWt = (float4*)smem;            // bilinear corner weights (mask folded)
    float*  sV  = smem + 288*4;             // V[kk][p], kk = c*9+k, padded stride 33
    float*  sW  = sV + 603*33;              // weight chunk [64][68]
    int*    sIdx= (int*)(sW + 64*68);       // packed clamped corner indices

    int tid = threadIdx.x;
    int b = blockIdx.z, y = blockIdx.y, x0 = blockIdx.x*32;

    // ---- Phase A: bilinear meta for 32 pixels x 9 taps ----
    for (int e = tid; e < 288; e += 256) {
        int p = e & 31, k = e >> 5;
        int x = x0 + p;
        int pix = y*128 + x;
        float offy = g_off [(b*18 + 2*k    )*HW + pix];
        float offx = g_off [(b*18 + 2*k + 1)*HW + pix];
        float m    = g_mask[(b*9  + k      )*HW + pix];
        int ky = k / 3, kx = k - ky*3;
        float py = (float)(y + ky - 1) + offy;
        float px = (float)(x + kx - 1) + offx;
        float fy = floorf(py), fx = floorf(px);
        float wy = py - fy,    wx = px - fx;
        int iy = (int)fy, ix = (int)fx;
        bool vy0 = (iy   >= 0 && iy   <= 127);
        bool vy1 = (iy+1 >= 0 && iy+1 <= 127);
        bool vx0 = (ix   >= 0 && ix   <= 127);
        bool vx1 = (ix+1 >= 0 && ix+1 <= 127);
        float4 wv;
        wv.x = (1.f-wy)*(1.f-wx)*m * ((vy0 && vx0) ? 1.f : 0.f);
        wv.y = (1.f-wy)*wx      *m * ((vy0 && vx1) ? 1.f : 0.f);
        wv.z = wy*(1.f-wx)      *m * ((vy1 && vx0) ? 1.f : 0.f);
        wv.w = wy*wx            *m * ((vy1 && vx1) ? 1.f : 0.f);
        sWt[e] = wv;
        int iy0 = min(max(iy,   0), 127), iy1 = min(max(iy+1, 0), 127);
        int ix0 = min(max(ix,   0), 127), ix1 = min(max(ix+1, 0), 127);
        sIdx[e] = iy0 | (iy1 << 8) | (ix0 << 16) | (ix1 << 24);
    }
    __syncthreads();

    // ---- Phase B: gather V[603][32] ----
    const float* xb = xin + b*64*HW;
    const float* lb = lr  + b*3*HW;
    for (int e = tid; e < 19296; e += 256) {     // 603*32
        int p = e & 31, kk = e >> 5;
        int c = kk / 9, k = kk - c*9;
        int mi = (k << 5) | p;
        float4 wt = sWt[mi];
        int pk = sIdx[mi];
        int iy0 =  pk        & 255, iy1 = (pk >> 8)  & 255;
        int ix0 = (pk >> 16) & 255, ix1 = (pk >> 24) & 255;
        const float* src = (c < 64) ? (xb + c*HW) : (lb + (c-64)*HW);
        float v = wt.x * __ldg(src + iy0*128 + ix0)
                + wt.y * __ldg(src + iy0*128 + ix1)
                + wt.z * __ldg(src + iy1*128 + ix0)
                + wt.w * __ldg(src + iy1*128 + ix1);
        sV[kk*33 + p] = v;
    }
    __syncthreads();

    // ---- Phase C: out[64][32] = W[64][603] * V[603][32] ----
    int p = tid & 31, og = tid >> 5;             // 8 output channels per thread
    float acc[8];
    #pragma unroll
    for (int q = 0; q < 8; q++) acc[q] = 0.f;
    for (int c0 = 0; c0 < 603; c0 += 67) {
        for (int i = tid; i < 64*67; i += 256) {
            int o = i / 67, j = i - o*67;
            sW[o*68 + j] = wmain[o*603 + c0 + j];
        }
        __syncthreads();
        const float* vp = sV + c0*33 + p;
        const float* wp = sW + og*8*68;
        #pragma unroll
        for (int j = 0; j < 67; j++) {
            float v = vp[j*33];
            #pragma unroll
            for (int q = 0; q < 8; q++)
                acc[q] = fmaf(wp[q*68 + j], v, acc[q]);
        }
        __syncthreads();
    }
    int pix = y*128 + x0 + p;
    #pragma unroll
    for (int q = 0; q < 8; q++) {
        int o = og*8 + q;
        out[(b*64 + o)*HW + pix] = acc[q] + bias[o];
    }
}

// ---------------- 4) global average pool over H,W -----------------------------
__global__ void pool_kernel(const float* __restrict__ xf)
{
    __shared__ float red[256];
    int bc = blockIdx.x, tid = threadIdx.x;
    float s = 0.f;
    const float* p = xf + bc*HW;
    for (int i = tid; i < HW; i += 256) s += p[i];
    red[tid] = s; __syncthreads();
    for (int st = 128; st > 0; st >>= 1) {
        if (tid < st) red[tid] += red[tid + st];
        __syncthreads();
    }
    if (tid == 0) g_pool[bc] = red[0] * (1.f/HW);
}

// ---------------- 5) channel-filter MLP (tiny) --------------------------------
__global__ void ch_kernel(const float* __restrict__ ch_w1, const float* __restrict__ ch_b1,
                          const float* __restrict__ ch_w2, const float* __restrict__ ch_b2)
{
    int t = threadIdx.x;
    if (t >= 64) return;
    int b = t >> 4, s = t & 15;
    float h1[4];
    #pragma unroll
    for (int m = 0; m < 4; m++) {
        float a = ch_b1[s*4 + m];
        #pragma unroll
        for (int c = 0; c < 3; c++) a = fmaf(g_pool[b*3 + c], ch_w1[(s*4 + m)*3 + c], a);
        h1[m] = fmaxf(a, 0.f);
    }
    for (int k = 0; k < 27; k++) {
        float a = ch_b2[s*27 + k];
        #pragma unroll
        for (int m = 0; m < 4; m++) a = fmaf(h1[m], ch_w2[(s*27 + k)*4 + m], a);
        g_ch[(b*16 + s)*27 + k] = a;
    }
}

// ---------------- 6) DDF up: fused sp-conv + dynamic filter + pixel shuffle ---
__global__ __launch_bounds__(256) void ddf_kernel(
    const float* __restrict__ spw, const float* __restrict__ spb,
    float* __restrict__ out)
{
    __shared__ float sSpw[3888];
    __shared__ float sSpb[144];
    __shared__ float sCh[432];
    int b = blockIdx.y, tid = threadIdx.x;
    for (int i = tid; i < 3888; i += 256) sSpw[i] = spw[i];
    if (tid < 144) sSpb[tid] = spb[tid];
    for (int i = tid; i < 432; i += 256) sCh[i] = g_ch[b*432 + i];
    __syncthreads();

    int pix = blockIdx.x*256 + tid;
    int x = pix & 127, y = pix >> 7;
    const float* xb = g_xfin + b*3*HW;

    float win[27];
    #pragma unroll
    for (int c = 0; c < 3; c++)
        #pragma unroll
        for (int r = 0; r < 3; r++) {
            int yy = y + r - 1;
            #pragma unroll
            for (int q = 0; q < 3; q++) {
                int xx = x + q - 1;
                win[c*9 + r*3 + q] = (yy >= 0 && yy < 128 && xx >= 0 && xx < 128)
                                   ? xb[c*HW + yy*128 + xx] : 0.f;
            }
        }

    float* ob = out + b*3*(512*512);
    #pragma unroll 1
    for (int s = 0; s < 16; s++) {
        float a0 = 0.f, a1 = 0.f, a2 = 0.f;
        #pragma unroll
        for (int k = 0; k < 9; k++) {
            float spv = sSpb[s*9 + k];
            const float* wrow = sSpw + (s*9 + k)*27;
            #pragma unroll
            for (int j = 0; j < 27; j++) spv = fmaf(wrow[j], win[j], spv);
            a0 = fmaf(win[k],      sCh[s*27 + k]      + spv, a0);
            a1 = fmaf(win[9 + k],  sCh[s*27 + 9 + k]  + spv, a1);
            a2 = fmaf(win[18 + k], sCh[s*27 + 18 + k] + spv, a2);
        }
        int oy = (y << 2) + (s >> 2), ox = (x << 2) + (s & 3);
        ob[0*262144 + oy*512 + ox] = fminf(fmaxf(a0, 0.f), 255.f);
        ob[1*262144 + oy*512 + ox] = fminf(fmaxf(a1, 0.f), 255.f);
        ob[2*262144 + oy*512 + ox] = fminf(fmaxf(a2, 0.f), 255.f);
    }
}

// ---------------- host orchestration ------------------------------------------
extern "C" void kernel_launch(void* const* d_in, const int* in_sizes, int n_in,
                              void* d_out, int out_size)
{
    const float* X      = (const float*)d_in[0];
    const float* lstm_w = (const float*)d_in[1];
    const float* lstm_b = (const float*)d_in[2];
    const float* dw[3][6];
    for (int i = 0; i < 3; i++)
        for (int j = 0; j < 6; j++)
            dw[i][j] = (const float*)d_in[3 + i*6 + j];   // ow, ob, mw, mb, w, b
    const float* conv_w = (const float*)d_in[21];
    const float* conv_b = (const float*)d_in[22];
    const float* sp_w   = (const float*)d_in[23];
    const float* sp_b   = (const float*)d_in[24];
    const float* ch_w1  = (const float*)d_in[25];
    const float* ch_b1  = (const float*)d_in[26];
    const float* ch_w2  = (const float*)d_in[27];
    const float* ch_b2  = (const float*)d_in[28];

    float* out_main = (float*)d_out;                     // [4,3,512,512]
    float* hid      = out_main + 4*3*512*512;            // [4,64,128,128]
    float* cell     = hid + 4*64*128*128;                // [4,64,128,128]

    void *pxb0, *pxb1;
    cudaGetSymbolAddress(&pxb0, g_xbuf0);
    cudaGetSymbolAddress(&pxb1, g_xbuf1);
    float* xb0 = (float*)pxb0;
    float* xb1 = (float*)pxb1;
    void *poff, *pmask, *pxfin;
    cudaGetSymbolAddress(&poff,  g_off);
    cudaGetSymbolAddress(&pmask, g_mask);
    cudaGetSymbolAddress(&pxfin, g_xfin);
    float* off_p  = (float*)poff;
    float* mask_p = (float*)pmask;
    float* xfin_p = (float*)pxfin;

    cudaFuncSetAttribute(deform_kernel, cudaFuncAttributeMaxDynamicSharedMemorySize,
                         DSMEM_BYTES);

    dim3 convGrid(4, 16, B_);
    dim3 defGrid(4, 128, B_);

    // 1) ConvLSTM -> hid, cell (both are outputs; hid also feeds stage 1)
    lstm_kernel<<<16384, 256>>>(X, lstm_w, lstm_b, hid, cell);

    // 2) stage 1
    conv67_kernel<27,18,0><<<convGrid, 256>>>(hid, X, dw[0][0], dw[0][1],
                                              dw[0][2], dw[0][3], off_p, mask_p);
    deform_kernel<<<defGrid, 256, DSMEM_BYTES>>>(hid, X, dw[0][4], dw[0][5], xb0);

    // 3) stage 2
    conv67_kernel<27,18,0><<<convGrid, 256>>>(xb0, X, dw[1][0], dw[1][1],
                                              dw[1][2], dw[1][3], off_p, mask_p);
    deform_kernel<<<defGrid, 256, DSMEM_BYTES>>>(xb0, X, dw[1][4], dw[1][5], xb1);

    // 4) stage 3
    conv67_kernel<27,18,0><<<convGrid, 256>>>(xb1, X, dw[2][0], dw[2][1],
                                              dw[2][2], dw[2][3], off_p, mask_p);
    deform_kernel<<<defGrid, 256, DSMEM_BYTES>>>(xb1, X, dw[2][4], dw[2][5], xb0);

    // 5) fuse conv -> 3 channels
    conv67_kernel<3,3,1><<<convGrid, 256>>>(xb0, X, conv_w, conv_b,
                                            conv_w, conv_b, xfin_p, xfin_p);

    // 6) DDF up
    pool_kernel<<<B_*3, 256>>>(xfin_p);
    ch_kernel<<<1, 64>>>(ch_w1, ch_b1, ch_w2, ch_b2);
    ddf_kernel<<<dim3(64, B_), 256>>>(sp_w, sp_b, out_main);
}

// round 2
// speedup vs baseline: 1.0664x; 1.0664x over previous
#include <cuda_runtime.h>
#include <math.h>

#define HW   16384
#define B_   4

// ---------------- scratch ------------------------------------------------------
__device__ float g_xbuf0[B_*64*HW];
__device__ float g_xbuf1[B_*64*HW];
__device__ float g_off  [B_*18*HW];
__device__ float g_mask [B_*9*HW];
__device__ float g_xfin [B_*3*HW];
__device__ float g_ch   [B_*16*27];
__device__ float g_pool [B_*3];

__device__ __forceinline__ float sigm(float v){ return 1.f/(1.f+__expf(-v)); }

// ---------------- 1) ConvLSTM (h=c=0 => only 3 input channels, no f gate) -----
__global__ void lstm_kernel(const float* __restrict__ X, const float* __restrict__ w,
                            const float* __restrict__ bias,
                            float* __restrict__ hid, float* __restrict__ cell)
{
    int idx = blockIdx.x*256 + threadIdx.x;            // [b][k][y][x]
    int x = idx & 127, y = (idx >> 7) & 127, k = (idx >> 14) & 63, b = idx >> 20;
    float ai = bias[k], ao = bias[128+k], ag = bias[192+k];
    const float* Xb = X + b*3*HW;
    const float* wi = w + k*603;
    const float* wo = w + (128+k)*603;
    const float* wg = w + (192+k)*603;
    #pragma unroll
    for (int c = 0; c < 3; c++)
        #pragma unroll
        for (int dy = 0; dy < 3; dy++) {
            int yy = y + dy - 1;
            #pragma unroll
            for (int dx = 0; dx < 3; dx++) {
                int xx = x + dx - 1;
                float v = (yy >= 0 && yy < 128 && xx >= 0 && xx < 128)
                        ? Xb[c*HW + yy*128 + xx] : 0.f;
                int t = c*9 + dy*3 + dx;
                ai = fmaf(wi[t], v, ai);
                ao = fmaf(wo[t], v, ao);
                ag = fmaf(wg[t], v, ag);
            }
        }
    float cc = sigm(ai)*tanhf(ag);
    float hh = sigm(ao)*tanhf(cc);
    hid[idx]  = hh;
    cell[idx] = cc;
}

// ---------------- 2) offset/mask conv as register-tiled GEMM ------------------
// out[18] = raw offsets, out[18..27) = 2*sigmoid mask. 32-out padded GEMM.
// Block: 128 threads; strip = 64 px of one row. Thread tile: 4 outs x 4 px.
__global__ __launch_bounds__(128) void conv_off_kernel(
    const float* __restrict__ xin, const float* __restrict__ lr,
    const float* __restrict__ w0, const float* __restrict__ b0,
    const float* __restrict__ w1, const float* __restrict__ b1,
    float* __restrict__ out0, float* __restrict__ out1)
{
    __shared__ float sTile[16*204];     // 16ch x 3rows x 68cols (cols 0..65 valid)
    __shared__ float sW[16*9*32];       // transposed: [tap_idx][32 outs]

    int tid = threadIdx.x;
    int pg = tid & 15;                  // pixel group (4 px)
    int og = tid >> 4;                  // out group (4 outs)
    int b = blockIdx.z, y = blockIdx.y;
    int x0 = blockIdx.x*64;
    int gx0 = x0 - 1, y0 = y - 1;

    float acc[4][4];
    #pragma unroll
    for (int q = 0; q < 4; q++)
        #pragma unroll
        for (int p = 0; p < 4; p++) acc[q][p] = 0.f;

    for (int c0 = 0; c0 < 67; c0 += 16) {
        int cnt = (67 - c0) < 16 ? (67 - c0) : 16;
        // stage input tile (68-wide rows, zero-padded)
        for (int i = tid; i < cnt*204; i += 128) {
            int c = i / 204, rem = i - c*204;
            int r = rem / 68, col = rem - r*68;
            int gy = y0 + r, gx = gx0 + col;
            int cg = c0 + c;
            const float* src = (cg < 64) ? (xin + (b*64 + cg)*HW)
                                         : (lr  + (b*3 + (cg-64))*HW);
            sTile[i] = (col < 66 && gy >= 0 && gy < 128 && gx >= 0 && gx < 128)
                     ? src[gy*128 + gx] : 0.f;
        }
        // stage weights transposed [tap][out]
        int c09 = c0*9;
        for (int i = tid; i < cnt*9*32; i += 128) {
            int o = i & 31, tdx = i >> 5;
            float wv = 0.f;
            if (o < 18)      wv = w0[o*603 + c09 + tdx];
            else if (o < 27) wv = w1[(o-18)*603 + c09 + tdx];
            sW[tdx*32 + o] = wv;
        }
        __syncthreads();

        const float* tbase = sTile + pg*4;
        for (int c = 0; c < cnt; c++) {
            #pragma unroll
            for (int ky = 0; ky < 3; ky++) {
                const float* rb = tbase + c*204 + ky*68;
                float4 a4 = *(const float4*)rb;
                float2 a2 = *(const float2*)(rb + 4);
                float win[6] = {a4.x, a4.y, a4.z, a4.w, a2.x, a2.y};
                #pragma unroll
                for (int kx = 0; kx < 3; kx++) {
                    float4 w = *(const float4*)(sW + (c*9 + ky*3 + kx)*32 + og*4);
                    #pragma unroll
                    for (int p = 0; p < 4; p++) {
                        float v = win[kx + p];
                        acc[0][p] = fmaf(w.x, v, acc[0][p]);
                        acc[1][p] = fmaf(w.y, v, acc[1][p]);
                        acc[2][p] = fmaf(w.z, v, acc[2][p]);
                        acc[3][p] = fmaf(w.w, v, acc[3][p]);
                    }
                }
            }
        }
        __syncthreads();
    }

    int pixb = y*128 + x0 + pg*4;
    #pragma unroll
    for (int q = 0; q < 4; q++) {
        int o = og*4 + q;
        if (o < 18) {
            float bb = b0[o];
            float4 r = make_float4(acc[q][0]+bb, acc[q][1]+bb, acc[q][2]+bb, acc[q][3]+bb);
            *(float4*)(out0 + (b*18 + o)*HW + pixb) = r;
        } else if (o < 27) {
            float bb = b1[o-18];
            float4 r = make_float4(2.f*sigm(acc[q][0]+bb), 2.f*sigm(acc[q][1]+bb),
                                   2.f*sigm(acc[q][2]+bb), 2.f*sigm(acc[q][3]+bb));
            *(float4*)(out1 + (b*9 + (o-18))*HW + pixb) = r;
        }
    }
}

// ---------------- 2b) small direct conv (final 3-out fuse conv) ---------------
template<int COUT>
__global__ __launch_bounds__(256) void conv_small_kernel(
    const float* __restrict__ xin, const float* __restrict__ lr,
    const float* __restrict__ w0, const float* __restrict__ b0,
    float* __restrict__ out0)
{
    __shared__ float sT[16*10*34];
    __shared__ float sW[COUT*16*9];
    int tid = threadIdx.x;
    int tx = tid & 31, ty = tid >> 5;
    int b = blockIdx.z;
    int x = blockIdx.x*32 + tx, y = blockIdx.y*8 + ty;
    int gx0 = blockIdx.x*32 - 1, gy0 = blockIdx.y*8 - 1;

    float acc[COUT];
    #pragma unroll
    for (int o = 0; o < COUT; o++) acc[o] = 0.f;

    for (int c0 = 0; c0 < 67; c0 += 16) {
        int cnt = (67 - c0) < 16 ? (67 - c0) : 16;
        for (int i = tid; i < cnt*340; i += 256) {
            int c = i / 340, rem = i - c*340;
            int r = rem / 34, col = rem - r*34;
            int gy = gy0 + r, gx = gx0 + col;
            int cg = c0 + c;
            const float* src = (cg < 64) ? (xin + (b*64 + cg)*HW)
                                         : (lr  + (b*3 + (cg-64))*HW);
            sT[i] = (gy >= 0 && gy < 128 && gx >= 0 && gx < 128)
                  ? src[gy*128 + gx] : 0.f;
        }
        int wtot = COUT*cnt*9;
        for (int i = tid; i < wtot; i += 256) {
            int o = i / (cnt*9), rem = i - o*(cnt*9);
            sW[o*144 + rem] = w0[o*603 + c0*9 + rem];
        }
        __syncthreads();
        for (int c = 0; c < cnt; c++) {
            float win[9];
            #pragma unroll
            for (int r = 0; r < 3; r++)
                #pragma unroll
                for (int q = 0; q < 3; q++)
                    win[r*3+q] = sT[c*340 + (ty+r)*34 + (tx+q)];
            #pragma unroll
            for (int o = 0; o < COUT; o++) {
                #pragma unroll
                for (int t = 0; t < 9; t++)
                    acc[o] = fmaf(sW[o*144 + c*9 + t], win[t], acc[o]);
            }
        }
        __syncthreads();
    }
    int pix = y*128 + x;
    #pragma unroll
    for (int o = 0; o < COUT; o++)
        out0[(b*COUT + o)*HW + pix] = acc[o] + b0[o];
}

// ---------------- 3) deformable gather + 64x603 GEMM per 32-pixel strip ------
// dyn smem: sWt float4[288] | sV[603*34 +2 pad] | sWc[67*64] | sIdx[288]
#define SV_OFF   1152
#define SWC_OFF  (1152 + 20504)
#define SIDX_OFF (SWC_OFF + 4288)
#define DSMEM_BYTES ((SIDX_OFF + 288) * 4)

__global__ __launch_bounds__(256) void deform_kernel(
    const float* __restrict__ xin, const float* __restrict__ lr,
    const float* __restrict__ wmain, const float* __restrict__ bias,
    float* __restrict__ out)
{
    extern __shared__ float smem[];
    float4* sWt = (float4*)smem;
    float*  sV  = smem + SV_OFF;            // V[kk][p], stride 34
    float*  sWc = smem + SWC_OFF;           // transposed weight chunk [j][64]
    int*    sIdx= (int*)(smem + SIDX_OFF);

    int tid = threadIdx.x;
    int b = blockIdx.z, y = blockIdx.y, x0 = blockIdx.x*32;

    // ---- Phase A: bilinear meta ----
    for (int e = tid; e < 288; e += 256) {
        int p = e & 31, k = e >> 5;
        int x = x0 + p;
        int pix = y*128 + x;
        float offy = g_off [(b*18 + 2*k    )*HW + pix];
        float offx = g_off [(b*18 + 2*k + 1)*HW + pix];
        float m    = g_mask[(b*9  + k      )*HW + pix];
        int ky = k / 3, kx = k - ky*3;
        float py = (float)(y + ky - 1) + offy;
        float px = (float)(x + kx - 1) + offx;
        float fy = floorf(py), fx = floorf(px);
        float wy = py - fy,    wx = px - fx;
        int iy = (int)fy, ix = (int)fx;
        bool vy0 = (iy   >= 0 && iy   <= 127);
        bool vy1 = (iy+1 >= 0 && iy+1 <= 127);
        bool vx0 = (ix   >= 0 && ix   <= 127);
        bool vx1 = (ix+1 >= 0 && ix+1 <= 127);
        float4 wv;
        wv.x = (1.f-wy)*(1.f-wx)*m * ((vy0 && vx0) ? 1.f : 0.f);
        wv.y = (1.f-wy)*wx      *m * ((vy0 && vx1) ? 1.f : 0.f);
        wv.z = wy*(1.f-wx)      *m * ((vy1 && vx0) ? 1.f : 0.f);
        wv.w = wy*wx            *m * ((vy1 && vx1) ? 1.f : 0.f);
        sWt[e] = wv;
        int iy0 = min(max(iy,   0), 127), iy1 = min(max(iy+1, 0), 127);
        int ix0 = min(max(ix,   0), 127), ix1 = min(max(ix+1, 0), 127);
        sIdx[e] = iy0 | (iy1 << 8) | (ix0 << 16) | (ix1 << 24);
    }
    __syncthreads();

    // ---- Phase B: gather V[603][32] ----
    const float* xb = xin + b*64*HW;
    const float* lb = lr  + b*3*HW;
    for (int e = tid; e < 19296; e += 256) {
        int p = e & 31, kk = e >> 5;
        int c = kk / 9, k = kk - c*9;
        int mi = (k << 5) | p;
        float4 wt = sWt[mi];
        int pk = sIdx[mi];
        int iy0 =  pk        & 255, iy1 = (pk >> 8)  & 255;
        int ix0 = (pk >> 16) & 255, ix1 = (pk >> 24) & 255;
        const float* src = (c < 64) ? (xb + c*HW) : (lb + (c-64)*HW);
        float v = wt.x * __ldg(src + iy0*128 + ix0)
                + wt.y * __ldg(src + iy0*128 + ix1)
                + wt.z * __ldg(src + iy1*128 + ix0)
                + wt.w * __ldg(src + iy1*128 + ix1);
        sV[kk*34 + p] = v;
    }
    __syncthreads();

    // ---- Phase C: out[64][32] = W[64][603] * V[603][32], 4o x 2px tiles ----
    int pg = tid & 15, og = tid >> 4;
    float acc[4][2];
    #pragma unroll
    for (int q = 0; q < 4; q++) { acc[q][0] = 0.f; acc[q][1] = 0.f; }

    for (int c0 = 0; c0 < 603; c0 += 67) {
        for (int i = tid; i < 67*64; i += 256) {
            int o = i & 63, j = i >> 6;
            sWc[j*64 + o] = wmain[o*603 + c0 + j];
        }
        __syncthreads();
        const float* vp = sV + c0*34 + pg*2;
        const float* wp = sWc + og*4;
        #pragma unroll 8
        for (int j = 0; j < 67; j++) {
            float4 w = *(const float4*)(wp + j*64);
            float2 v = *(const float2*)(vp + j*34);
            acc[0][0] = fmaf(w.x, v.x, acc[0][0]);
            acc[0][1] = fmaf(w.x, v.y, acc[0][1]);
            acc[1][0] = fmaf(w.y, v.x, acc[1][0]);
            acc[1][1] = fmaf(w.y, v.y, acc[1][1]);
            acc[2][0] = fmaf(w.z, v.x, acc[2][0]);
            acc[2][1] = fmaf(w.z, v.y, acc[2][1]);
            acc[3][0] = fmaf(w.w, v.x, acc[3][0]);
            acc[3][1] = fmaf(w.w, v.y, acc[3][1]);
        }
        __syncthreads();
    }
    int pix = y*128 + x0 + pg*2;
    #pragma unroll
    for (int q = 0; q < 4; q++) {
        int o = og*4 + q;
        float bb = bias[o];
        float2 r = make_float2(acc[q][0] + bb, acc[q][1] + bb);
        *(float2*)(out + (b*64 + o)*HW + pix) = r;
    }
}

// ---------------- 4) global average pool --------------------------------------
__global__ void pool_kernel(const float* __restrict__ xf)
{
    __shared__ float red[256];
    int bc = blockIdx.x, tid = threadIdx.x;
    float s = 0.f;
    const float* p = xf + bc*HW;
    for (int i = tid; i < HW; i += 256) s += p[i];
    red[tid] = s; __syncthreads();
    for (int st = 128; st > 0; st >>= 1) {
        if (tid < st) red[tid] += red[tid + st];
        __syncthreads();
    }
    if (tid == 0) g_pool[bc] = red[0] * (1.f/HW);
}

// ---------------- 5) channel-filter MLP ---------------------------------------
__global__ void ch_kernel(const float* __restrict__ ch_w1, const float* __restrict__ ch_b1,
                          const float* __restrict__ ch_w2, const float* __restrict__ ch_b2)
{
    int t = threadIdx.x;
    if (t >= 64) return;
    int b = t >> 4, s = t & 15;
    float h1[4];
    #pragma unroll
    for (int m = 0; m < 4; m++) {
        float a = ch_b1[s*4 + m];
        #pragma unroll
        for (int c = 0; c < 3; c++) a = fmaf(g_pool[b*3 + c], ch_w1[(s*4 + m)*3 + c], a);
        h1[m] = fmaxf(a, 0.f);
    }
    for (int k = 0; k < 27; k++) {
        float a = ch_b2[s*27 + k];
        #pragma unroll
        for (int m = 0; m < 4; m++) a = fmaf(h1[m], ch_w2[(s*27 + k)*4 + m], a);
        g_ch[(b*16 + s)*27 + k] = a;
    }
}

// ---------------- 6) DDF up ----------------------------------------------------
__global__ __launch_bounds__(256) void ddf_kernel(
    const float* __restrict__ spw, const float* __restrict__ spb,
    float* __restrict__ out)
{
    __shared__ float sSpw[144*28];          // rows padded to 28 (16B-aligned)
    __shared__ float sSpb[144];
    __shared__ float sCh[432];
    int b = blockIdx.y, tid = threadIdx.x;
    for (int i = tid; i < 144*28; i += 256) {
        int row = i / 28, col = i - row*28;
        sSpw[i] = (col < 27) ? spw[row*27 + col] : 0.f;
    }
    if (tid < 144) sSpb[tid] = spb[tid];
    for (int i = tid; i < 432; i += 256) sCh[i] = g_ch[b*432 + i];
    __syncthreads();

    int pix = blockIdx.x*256 + tid;
    int x = pix & 127, y = pix >> 7;
    const float* xb = g_xfin + b*3*HW;

    float win[28];
    win[27] = 0.f;
    #pragma unroll
    for (int c = 0; c < 3; c++)
        #pragma unroll
        for (int r = 0; r < 3; r++) {
            int yy = y + r - 1;
            #pragma unroll
            for (int q = 0; q < 3; q++) {
                int xx = x + q - 1;
                win[c*9 + r*3 + q] = (yy >= 0 && yy < 128 && xx >= 0 && xx < 128)
                                   ? xb[c*HW + yy*128 + xx] : 0.f;
            }
        }

    float* ob = out + b*3*(512*512);
    #pragma unroll 1
    for (int s = 0; s < 16; s++) {
        float a0 = 0.f, a1 = 0.f, a2 = 0.f;
        #pragma unroll
        for (int k = 0; k < 9; k++) {
            float spv = sSpb[s*9 + k];
            const float4* w4 = (const float4*)(sSpw + (s*9 + k)*28);
            #pragma unroll
            for (int j4 = 0; j4 < 7; j4++) {
                float4 w = w4[j4];
                spv = fmaf(w.x, win[j4*4 + 0], spv);
                spv = fmaf(w.y, win[j4*4 + 1], spv);
                spv = fmaf(w.z, win[j4*4 + 2], spv);
                spv = fmaf(w.w, win[j4*4 + 3], spv);
            }
            a0 = fmaf(win[k],      sCh[s*27 + k]      + spv, a0);
            a1 = fmaf(win[9 + k],  sCh[s*27 + 9 + k]  + spv, a1);
            a2 = fmaf(win[18 + k], sCh[s*27 + 18 + k] + spv, a2);
        }
        int oy = (y << 2) + (s >> 2), ox = (x << 2) + (s & 3);
        ob[0*262144 + oy*512 + ox] = fminf(fmaxf(a0, 0.f), 255.f);
        ob[1*262144 + oy*512 + ox] = fminf(fmaxf(a1, 0.f), 255.f);
        ob[2*262144 + oy*512 + ox] = fminf(fmaxf(a2, 0.f), 255.f);
    }
}

// ---------------- host orchestration ------------------------------------------
extern "C" void kernel_launch(void* const* d_in, const int* in_sizes, int n_in,
                              void* d_out, int out_size)
{
    const float* X      = (const float*)d_in[0];
    const float* lstm_w = (const float*)d_in[1];
    const float* lstm_b = (const float*)d_in[2];
    const float* dw[3][6];
    for (int i = 0; i < 3; i++)
        for (int j = 0; j < 6; j++)
            dw[i][j] = (const float*)d_in[3 + i*6 + j];   // ow, ob, mw, mb, w, b
    const float* conv_w = (const float*)d_in[21];
    const float* conv_b = (const float*)d_in[22];
    const float* sp_w   = (const float*)d_in[23];
    const float* sp_b   = (const float*)d_in[24];
    const float* ch_w1  = (const float*)d_in[25];
    const float* ch_b1  = (const float*)d_in[26];
    const float* ch_w2  = (const float*)d_in[27];
    const float* ch_b2  = (const float*)d_in[28];

    float* out_main = (float*)d_out;                     // [4,3,512,512]
    float* hid      = out_main + 4*3*512*512;            // [4,64,128,128]
    float* cell     = hid + 4*64*128*128;                // [4,64,128,128]

    void *pxb0, *pxb1, *poff, *pmask, *pxfin;
    cudaGetSymbolAddress(&pxb0, g_xbuf0);
    cudaGetSymbolAddress(&pxb1, g_xbuf1);
    cudaGetSymbolAddress(&poff,  g_off);
    cudaGetSymbolAddress(&pmask, g_mask);
    cudaGetSymbolAddress(&pxfin, g_xfin);
    float* xb0 = (float*)pxb0;
    float* xb1 = (float*)pxb1;
    float* off_p  = (float*)poff;
    float* mask_p = (float*)pmask;
    float* xfin_p = (float*)pxfin;

    cudaFuncSetAttribute(deform_kernel, cudaFuncAttributeMaxDynamicSharedMemorySize,
                         DSMEM_BYTES);

    dim3 offGrid(2, 128, B_);     // 64-px strips
    dim3 convGrid(4, 16, B_);
    dim3 defGrid(4, 128, B_);

    lstm_kernel<<<16384, 256>>>(X, lstm_w, lstm_b, hid, cell);

    conv_off_kernel<<<offGrid, 128>>>(hid, X, dw[0][0], dw[0][1],
                                      dw[0][2], dw[0][3], off_p, mask_p);
    deform_kernel<<<defGrid, 256, DSMEM_BYTES>>>(hid, X, dw[0][4], dw[0][5], xb0);

    conv_off_kernel<<<offGrid, 128>>>(xb0, X, dw[1][0], dw[1][1],
                                      dw[1][2], dw[1][3], off_p, mask_p);
    deform_kernel<<<defGrid, 256, DSMEM_BYTES>>>(xb0, X, dw[1][4], dw[1][5], xb1);

    conv_off_kernel<<<offGrid, 128>>>(xb1, X, dw[2][0], dw[2][1],
                                      dw[2][2], dw[2][3], off_p, mask_p);
    deform_kernel<<<defGrid, 256, DSMEM_BYTES>>>(xb1, X, dw[2][4], dw[2][5], xb0);

    conv_small_kernel<3><<<convGrid, 256>>>(xb0, X, conv_w, conv_b, xfin_p);

    pool_kernel<<<B_*3, 256>>>(xfin_p);
    ch_kernel<<<1, 64>>>(ch_w1, ch_b1, ch_w2, ch_b2);
    ddf_kernel<<<dim3(64, B_), 256>>>(sp_w, sp_b, out_main);
}

// round 3
// speedup vs baseline: 1.4078x; 1.3201x over previous
#include <cuda_runtime.h>
#include <math.h>

#define HW   16384
#define B_   4

// ---------------- scratch ------------------------------------------------------
__device__ float g_xbuf0[B_*64*HW];
__device__ float g_xbuf1[B_*64*HW];
__device__ float g_off  [B_*18*HW];
__device__ float g_mask [B_*9*HW];
__device__ float g_xfin [B_*3*HW];
__device__ float g_ch   [B_*16*27];
__device__ float g_pool [B_*3];

__device__ __forceinline__ float sigm(float v){ return 1.f/(1.f+__expf(-v)); }

// ---- packed fp32x2 helpers (bit-exact fp32 FMA, 2 lanes per issue slot) ------
typedef unsigned long long ull;
__device__ __forceinline__ ull dup2(float v){
    ull r; asm("mov.b64 %0, {%1, %1};" : "=l"(r) : "f"(v)); return r;
}
__device__ __forceinline__ void ffma2(ull &d, ull a, ull b){
    asm("fma.rn.f32x2 %0, %1, %2, %0;" : "+l"(d) : "l"(a), "l"(b));
}
__device__ __forceinline__ float2 unpk(ull v){
    float2 f; asm("mov.b64 {%0, %1}, %2;" : "=f"(f.x), "=f"(f.y) : "l"(v)); return f;
}

// ---------------- 1) ConvLSTM (h=c=0 => only 3 input channels, no f gate) -----
__global__ void lstm_kernel(const float* __restrict__ X, const float* __restrict__ w,
                            const float* __restrict__ bias,
                            float* __restrict__ hid, float* __restrict__ cell)
{
    int idx = blockIdx.x*256 + threadIdx.x;            // [b][k][y][x]
    int x = idx & 127, y = (idx >> 7) & 127, k = (idx >> 14) & 63, b = idx >> 20;
    float ai = bias[k], ao = bias[128+k], ag = bias[192+k];
    const float* Xb = X + b*3*HW;
    const float* wi = w + k*603;
    const float* wo = w + (128+k)*603;
    const float* wg = w + (192+k)*603;
    #pragma unroll
    for (int c = 0; c < 3; c++)
        #pragma unroll
        for (int dy = 0; dy < 3; dy++) {
            int yy = y + dy - 1;
            #pragma unroll
            for (int dx = 0; dx < 3; dx++) {
                int xx = x + dx - 1;
                float v = (yy >= 0 && yy < 128 && xx >= 0 && xx < 128)
                        ? Xb[c*HW + yy*128 + xx] : 0.f;
                int t = c*9 + dy*3 + dx;
                ai = fmaf(wi[t], v, ai);
                ao = fmaf(wo[t], v, ao);
                ag = fmaf(wg[t], v, ag);
            }
        }
    float cc = sigm(ai)*tanhf(ag);
    float hh = sigm(ao)*tanhf(cc);
    hid[idx]  = hh;
    cell[idx] = cc;
}

// ---------------- 2) offset/mask conv, f32x2 packed GEMM ----------------------
// Block = 128 threads, one full 128-px row. Thread tile: 8 outs (4 pairs) x 4 px.
__global__ __launch_bounds__(128) void conv_off_kernel(
    const float* __restrict__ xin, const float* __restrict__ lr,
    const float* __restrict__ w0, const float* __restrict__ b0,
    const float* __restrict__ w1, const float* __restrict__ b1,
    float* __restrict__ out0, float* __restrict__ out1)
{
    __shared__ float sTile[16*3*132];    // 16ch x 3 rows x 132 cols
    __shared__ float sW[144*32];         // transposed [tap][32 outs] (pad out>=27 with 0)

    int tid = threadIdx.x;
    int pg = tid & 31;                   // 4 px each -> 128 px
    int og = tid >> 5;                   // 8 outs each (warp-uniform => LDS broadcast)
    int b = blockIdx.y, y = blockIdx.x;
    int y0 = y - 1;

    ull acc[4][4];                       // [out-pair][px]
    #pragma unroll
    for (int q = 0; q < 4; q++)
        #pragma unroll
        for (int p = 0; p < 4; p++) acc[q][p] = 0ull;

    for (int c0 = 0; c0 < 67; c0 += 16) {
        int cnt = (67 - c0) < 16 ? (67 - c0) : 16;
        // stage input rows (cols: gx = col-1, valid 0..127 -> col 1..128)
        for (int i = tid; i < cnt*396; i += 128) {
            int c = i / 396, rem = i - c*396;
            int r = rem / 132, col = rem - r*132;
            int gy = y0 + r, gx = col - 1;
            int cg = c0 + c;
            const float* src = (cg < 64) ? (xin + (b*64 + cg)*HW)
                                         : (lr  + (b*3 + (cg-64))*HW);
            sTile[i] = (gx >= 0 && gx < 128 && gy >= 0 && gy < 128)
                     ? src[gy*128 + gx] : 0.f;
        }
        // stage weights transposed
        int c09 = c0*9;
        for (int i = tid; i < cnt*288; i += 128) {
            int o = i & 31, tdx = i >> 5;
            float wv = 0.f;
            if (o < 18)      wv = w0[o*603 + c09 + tdx];
            else if (o < 27) wv = w1[(o-18)*603 + c09 + tdx];
            sW[tdx*32 + o] = wv;
        }
        __syncthreads();

        for (int c = 0; c < cnt; c++) {
            #pragma unroll
            for (int ky = 0; ky < 3; ky++) {
                const float* rb = sTile + c*396 + ky*132 + pg*4;
                float4 a4 = *(const float4*)rb;
                float2 a2 = *(const float2*)(rb + 4);
                ull vv[6];
                vv[0] = dup2(a4.x); vv[1] = dup2(a4.y); vv[2] = dup2(a4.z);
                vv[3] = dup2(a4.w); vv[4] = dup2(a2.x); vv[5] = dup2(a2.y);
                #pragma unroll
                for (int kx = 0; kx < 3; kx++) {
                    const float* wb = sW + (c*9 + ky*3 + kx)*32 + og*8;
                    ulonglong2 wA = *(const ulonglong2*)wb;
                    ulonglong2 wB = *(const ulonglong2*)(wb + 4);
                    #pragma unroll
                    for (int p = 0; p < 4; p++) {
                        ffma2(acc[0][p], wA.x, vv[kx + p]);
                        ffma2(acc[1][p], wA.y, vv[kx + p]);
                        ffma2(acc[2][p], wB.x, vv[kx + p]);
                        ffma2(acc[3][p], wB.y, vv[kx + p]);
                    }
                }
            }
        }
        __syncthreads();
    }

    int pixb = y*128 + pg*4;
    #pragma unroll
    for (int wp = 0; wp < 4; wp++) {
        int o0 = og*8 + 2*wp;
        float2 a0 = unpk(acc[wp][0]), a1 = unpk(acc[wp][1]);
        float2 a2 = unpk(acc[wp][2]), a3 = unpk(acc[wp][3]);
        // out o0
        if (o0 < 18) {
            float bb = b0[o0];
            *(float4*)(out0 + (b*18 + o0)*HW + pixb) =
                make_float4(a0.x+bb, a1.x+bb, a2.x+bb, a3.x+bb);
        } else if (o0 < 27) {
            float bb = b1[o0-18];
            *(float4*)(out1 + (b*9 + (o0-18))*HW + pixb) =
                make_float4(2.f*sigm(a0.x+bb), 2.f*sigm(a1.x+bb),
                            2.f*sigm(a2.x+bb), 2.f*sigm(a3.x+bb));
        }
        int o1 = o0 + 1;
        if (o1 < 18) {
            float bb = b0[o1];
            *(float4*)(out0 + (b*18 + o1)*HW + pixb) =
                make_float4(a0.y+bb, a1.y+bb, a2.y+bb, a3.y+bb);
        } else if (o1 < 27) {
            float bb = b1[o1-18];
            *(float4*)(out1 + (b*9 + (o1-18))*HW + pixb) =
                make_float4(2.f*sigm(a0.y+bb), 2.f*sigm(a1.y+bb),
                            2.f*sigm(a2.y+bb), 2.f*sigm(a3.y+bb));
        }
    }
}

// ---------------- 2b) small direct conv (final 3-out fuse conv) ---------------
template<int COUT>
__global__ __launch_bounds__(256) void conv_small_kernel(
    const float* __restrict__ xin, const float* __restrict__ lr,
    const float* __restrict__ w0, const float* __restrict__ b0,
    float* __restrict__ out0)
{
    __shared__ float sT[16*10*34];
    __shared__ float sW[COUT*16*9];
    int tid = threadIdx.x;
    int tx = tid & 31, ty = tid >> 5;
    int b = blockIdx.z;
    int x = blockIdx.x*32 + tx, y = blockIdx.y*8 + ty;
    int gx0 = blockIdx.x*32 - 1, gy0 = blockIdx.y*8 - 1;

    float acc[COUT];
    #pragma unroll
    for (int o = 0; o < COUT; o++) acc[o] = 0.f;

    for (int c0 = 0; c0 < 67; c0 += 16) {
        int cnt = (67 - c0) < 16 ? (67 - c0) : 16;
        for (int i = tid; i < cnt*340; i += 256) {
            int c = i / 340, rem = i - c*340;
            int r = rem / 34, col = rem - r*34;
            int gy = gy0 + r, gx = gx0 + col;
            int cg = c0 + c;
            const float* src = (cg < 64) ? (xin + (b*64 + cg)*HW)
                                         : (lr  + (b*3 + (cg-64))*HW);
            sT[i] = (gy >= 0 && gy < 128 && gx >= 0 && gx < 128)
                  ? src[gy*128 + gx] : 0.f;
        }
        int wtot = COUT*cnt*9;
        for (int i = tid; i < wtot; i += 256) {
            int o = i / (cnt*9), rem = i - o*(cnt*9);
            sW[o*144 + rem] = w0[o*603 + c0*9 + rem];
        }
        __syncthreads();
        for (int c = 0; c < cnt; c++) {
            float win[9];
            #pragma unroll
            for (int r = 0; r < 3; r++)
                #pragma unroll
                for (int q = 0; q < 3; q++)
                    win[r*3+q] = sT[c*340 + (ty+r)*34 + (tx+q)];
            #pragma unroll
            for (int o = 0; o < COUT; o++) {
                #pragma unroll
                for (int t = 0; t < 9; t++)
                    acc[o] = fmaf(sW[o*144 + c*9 + t], win[t], acc[o]);
            }
        }
        __syncthreads();
    }
    int pix = y*128 + x;
    #pragma unroll
    for (int o = 0; o < COUT; o++)
        out0[(b*COUT + o)*HW + pix] = acc[o] + b0[o];
}

// ---------------- 3) deform: gather + 64x603 GEMM, f32x2, K-chunked -----------
// Block = 256 thr, one 128-px row. Thread tile: 8 outs (4 pairs) x 4 px.
// smem floats: sWt 1152*4 | sIdx 1152 | sV 67*132 | sWc 67*64
#define DF_SIDX  4608
#define DF_SV    (4608 + 1152)
#define DF_SWC   (DF_SV + 67*132)
#define DF_SMEM_BYTES ((DF_SWC + 67*64) * 4)

__global__ __launch_bounds__(256) void deform_kernel(
    const float* __restrict__ xin, const float* __restrict__ lr,
    const float* __restrict__ wmain, const float* __restrict__ bias,
    float* __restrict__ out)
{
    extern __shared__ float smem[];
    float4* sWt = (float4*)smem;                 // [k][128 px] corner weights
    int*    sIdx= (int*)(smem + DF_SIDX);
    float*  sV  = smem + DF_SV;                  // [j][px], stride 132
    float*  sWc = smem + DF_SWC;                 // [j][64 outs]

    int tid = threadIdx.x;
    int b = blockIdx.y, y = blockIdx.x;

    // ---- Phase A: bilinear meta (9 taps x 128 px) ----
    for (int e = tid; e < 1152; e += 256) {
        int p = e & 127, k = e >> 7;
        int pix = y*128 + p;
        float offy = g_off [(b*18 + 2*k    )*HW + pix];
        float offx = g_off [(b*18 + 2*k + 1)*HW + pix];
        float m    = g_mask[(b*9  + k      )*HW + pix];
        int ky = k / 3, kx = k - ky*3;
        float py = (float)(y + ky - 1) + offy;
        float px = (float)(p + kx - 1) + offx;
        float fy = floorf(py), fx = floorf(px);
        float wy = py - fy,    wx = px - fx;
        int iy = (int)fy, ix = (int)fx;
        bool vy0 = (iy   >= 0 && iy   <= 127);
        bool vy1 = (iy+1 >= 0 && iy+1 <= 127);
        bool vx0 = (ix   >= 0 && ix   <= 127);
        bool vx1 = (ix+1 >= 0 && ix+1 <= 127);
        float4 wv;
        wv.x = (1.f-wy)*(1.f-wx)*m * ((vy0 && vx0) ? 1.f : 0.f);
        wv.y = (1.f-wy)*wx      *m * ((vy0 && vx1) ? 1.f : 0.f);
        wv.z = wy*(1.f-wx)      *m * ((vy1 && vx0) ? 1.f : 0.f);
        wv.w = wy*wx            *m * ((vy1 && vx1) ? 1.f : 0.f);
        sWt[e] = wv;
        int iy0 = min(max(iy,   0), 127), iy1 = min(max(iy+1, 0), 127);
        int ix0 = min(max(ix,   0), 127), ix1 = min(max(ix+1, 0), 127);
        sIdx[e] = iy0 | (iy1 << 8) | (ix0 << 16) | (ix1 << 24);
    }
    __syncthreads();

    const float* xb = xin + b*64*HW;
    const float* lb = lr  + b*3*HW;
    int pg = tid & 31, og = tid >> 5;

    ull acc[4][4];
    #pragma unroll
    for (int q = 0; q < 4; q++)
        #pragma unroll
        for (int p = 0; p < 4; p++) acc[q][p] = 0ull;

    for (int c0 = 0; c0 < 603; c0 += 67) {
        // stage weight chunk transposed
        for (int i = tid; i < 67*64; i += 256) {
            int o = i & 63, j = i >> 6;
            sWc[j*64 + o] = wmain[o*603 + c0 + j];
        }
        // gather V chunk [67][128]
        for (int e = tid; e < 67*128; e += 256) {
            int p = e & 127, j = e >> 7;
            int kk = c0 + j;
            int c = kk / 9, k = kk - c*9;
            int mi = (k << 7) | p;
            float4 wt = sWt[mi];
            int pk = sIdx[mi];
            int iy0 =  pk        & 255, iy1 = (pk >> 8)  & 255;
            int ix0 = (pk >> 16) & 255, ix1 = (pk >> 24) & 255;
            const float* src = (c < 64) ? (xb + c*HW) : (lb + (c-64)*HW);
            float v = wt.x * __ldg(src + iy0*128 + ix0)
                    + wt.y * __ldg(src + iy0*128 + ix1)
                    + wt.z * __ldg(src + iy1*128 + ix0)
                    + wt.w * __ldg(src + iy1*128 + ix1);
            sV[j*132 + p] = v;
        }
        __syncthreads();

        const float* vp = sV + pg*4;
        const float* wp_ = sWc + og*8;
        #pragma unroll 4
        for (int j = 0; j < 67; j++) {
            ulonglong2 wA = *(const ulonglong2*)(wp_ + j*64);
            ulonglong2 wB = *(const ulonglong2*)(wp_ + j*64 + 4);
            float4 v = *(const float4*)(vp + j*132);
            ull v0 = dup2(v.x), v1 = dup2(v.y), v2 = dup2(v.z), v3 = dup2(v.w);
            ffma2(acc[0][0], wA.x, v0); ffma2(acc[0][1], wA.x, v1);
            ffma2(acc[0][2], wA.x, v2); ffma2(acc[0][3], wA.x, v3);
            ffma2(acc[1][0], wA.y, v0); ffma2(acc[1][1], wA.y, v1);
            ffma2(acc[1][2], wA.y, v2); ffma2(acc[1][3], wA.y, v3);
            ffma2(acc[2][0], wB.x, v0); ffma2(acc[2][1], wB.x, v1);
            ffma2(acc[2][2], wB.x, v2); ffma2(acc[2][3], wB.x, v3);
            ffma2(acc[3][0], wB.y, v0); ffma2(acc[3][1], wB.y, v1);
            ffma2(acc[3][2], wB.y, v2); ffma2(acc[3][3], wB.y, v3);
        }
        __syncthreads();
    }

    int pixb = y*128 + pg*4;
    #pragma unroll
    for (int wp = 0; wp < 4; wp++) {
        int o0 = og*8 + 2*wp;
        float2 a0 = unpk(acc[wp][0]), a1 = unpk(acc[wp][1]);
        float2 a2 = unpk(acc[wp][2]), a3 = unpk(acc[wp][3]);
        float bb0 = bias[o0], bb1 = bias[o0+1];
        *(float4*)(out + (b*64 + o0)*HW + pixb) =
            make_float4(a0.x+bb0, a1.x+bb0, a2.x+bb0, a3.x+bb0);
        *(float4*)(out + (b*64 + o0+1)*HW + pixb) =
            make_float4(a0.y+bb1, a1.y+bb1, a2.y+bb1, a3.y+bb1);
    }
}

// ---------------- 4) global average pool --------------------------------------
__global__ void pool_kernel(const float* __restrict__ xf)
{
    __shared__ float red[256];
    int bc = blockIdx.x, tid = threadIdx.x;
    float s = 0.f;
    const float* p = xf + bc*HW;
    for (int i = tid; i < HW; i += 256) s += p[i];
    red[tid] = s; __syncthreads();
    for (int st = 128; st > 0; st >>= 1) {
        if (tid < st) red[tid] += red[tid + st];
        __syncthreads();
    }
    if (tid == 0) g_pool[bc] = red[0] * (1.f/HW);
}

// ---------------- 5) channel-filter MLP ---------------------------------------
__global__ void ch_kernel(const float* __restrict__ ch_w1, const float* __restrict__ ch_b1,
                          const float* __restrict__ ch_w2, const float* __restrict__ ch_b2)
{
    int t = threadIdx.x;
    if (t >= 64) return;
    int b = t >> 4, s = t & 15;
    float h1[4];
    #pragma unroll
    for (int m = 0; m < 4; m++) {
        float a = ch_b1[s*4 + m];
        #pragma unroll
        for (int c = 0; c < 3; c++) a = fmaf(g_pool[b*3 + c], ch_w1[(s*4 + m)*3 + c], a);
        h1[m] = fmaxf(a, 0.f);
    }
    for (int k = 0; k < 27; k++) {
        float a = ch_b2[s*27 + k];
        #pragma unroll
        for (int m = 0; m < 4; m++) a = fmaf(h1[m], ch_w2[(s*27 + k)*4 + m], a);
        g_ch[(b*16 + s)*27 + k] = a;
    }
}

// ---------------- 6) DDF up ----------------------------------------------------
__global__ __launch_bounds__(256) void ddf_kernel(
    const float* __restrict__ spw, const float* __restrict__ spb,
    float* __restrict__ out)
{
    __shared__ float sSpw[144*28];
    __shared__ float sSpb[144];
    __shared__ float sCh[432];
    int b = blockIdx.y, tid = threadIdx.x;
    for (int i = tid; i < 144*28; i += 256) {
        int row = i / 28, col = i - row*28;
        sSpw[i] = (col < 27) ? spw[row*27 + col] : 0.f;
    }
    if (tid < 144) sSpb[tid] = spb[tid];
    for (int i = tid; i < 432; i += 256) sCh[i] = g_ch[b*432 + i];
    __syncthreads();

    int pix = blockIdx.x*256 + tid;
    int x = pix & 127, y = pix >> 7;
    const float* xb = g_xfin + b*3*HW;

    float win[28];
    win[27] = 0.f;
    #pragma unroll
    for (int c = 0; c < 3; c++)
        #pragma unroll
        for (int r = 0; r < 3; r++) {
            int yy = y + r - 1;
            #pragma unroll
            for (int q = 0; q < 3; q++) {
                int xx = x + q - 1;
                win[c*9 + r*3 + q] = (yy >= 0 && yy < 128 && xx >= 0 && xx < 128)
                                   ? xb[c*HW + yy*128 + xx] : 0.f;
            }
        }

    float* ob = out + b*3*(512*512);
    #pragma unroll 1
    for (int s = 0; s < 16; s++) {
        float a0 = 0.f, a1 = 0.f, a2 = 0.f;
        #pragma unroll
        for (int k = 0; k < 9; k++) {
            float spv = sSpb[s*9 + k];
            const float4* w4 = (const float4*)(sSpw + (s*9 + k)*28);
            #pragma unroll
            for (int j4 = 0; j4 < 7; j4++) {
                float4 w = w4[j4];
                spv = fmaf(w.x, win[j4*4 + 0], spv);
                spv = fmaf(w.y, win[j4*4 + 1], spv);
                spv = fmaf(w.z, win[j4*4 + 2], spv);
                spv = fmaf(w.w, win[j4*4 + 3], spv);
            }
            a0 = fmaf(win[k],      sCh[s*27 + k]      + spv, a0);
            a1 = fmaf(win[9 + k],  sCh[s*27 + 9 + k]  + spv, a1);
            a2 = fmaf(win[18 + k], sCh[s*27 + 18 + k] + spv, a2);
        }
        int oy = (y << 2) + (s >> 2), ox = (x << 2) + (s & 3);
        ob[0*262144 + oy*512 + ox] = fminf(fmaxf(a0, 0.f), 255.f);
        ob[1*262144 + oy*512 + ox] = fminf(fmaxf(a1, 0.f), 255.f);
        ob[2*262144 + oy*512 + ox] = fminf(fmaxf(a2, 0.f), 255.f);
    }
}

// ---------------- host orchestration ------------------------------------------
extern "C" void kernel_launch(void* const* d_in, const int* in_sizes, int n_in,
                              void* d_out, int out_size)
{
    const float* X      = (const float*)d_in[0];
    const float* lstm_w = (const float*)d_in[1];
    const float* lstm_b = (const float*)d_in[2];
    const float* dw[3][6];
    for (int i = 0; i < 3; i++)
        for (int j = 0; j < 6; j++)
            dw[i][j] = (const float*)d_in[3 + i*6 + j];   // ow, ob, mw, mb, w, b
    const float* conv_w = (const float*)d_in[21];
    const float* conv_b = (const float*)d_in[22];
    const float* sp_w   = (const float*)d_in[23];
    const float* sp_b   = (const float*)d_in[24];
    const float* ch_w1  = (const float*)d_in[25];
    const float* ch_b1  = (const float*)d_in[26];
    const float* ch_w2  = (const float*)d_in[27];
    const float* ch_b2  = (const float*)d_in[28];

    float* out_main = (float*)d_out;                     // [4,3,512,512]
    float* hid      = out_main + 4*3*512*512;            // [4,64,128,128]
    float* cell     = hid + 4*64*128*128;                // [4,64,128,128]

    void *pxb0, *pxb1, *poff, *pmask, *pxfin;
    cudaGetSymbolAddress(&pxb0, g_xbuf0);
    cudaGetSymbolAddress(&pxb1, g_xbuf1);
    cudaGetSymbolAddress(&poff,  g_off);
    cudaGetSymbolAddress(&pmask, g_mask);
    cudaGetSymbolAddress(&pxfin, g_xfin);
    float* xb0 = (float*)pxb0;
    float* xb1 = (float*)pxb1;
    float* off_p  = (float*)poff;
    float* mask_p = (float*)pmask;
    float* xfin_p = (float*)pxfin;

    cudaFuncSetAttribute(deform_kernel, cudaFuncAttributeMaxDynamicSharedMemorySize,
                         DF_SMEM_BYTES);

    dim3 rowGrid(128, B_);
    dim3 convGrid(4, 16, B_);

    lstm_kernel<<<16384, 256>>>(X, lstm_w, lstm_b, hid, cell);

    conv_off_kernel<<<rowGrid, 128>>>(hid, X, dw[0][0], dw[0][1],
                                      dw[0][2], dw[0][3], off_p, mask_p);
    deform_kernel<<<rowGrid, 256, DF_SMEM_BYTES>>>(hid, X, dw[0][4], dw[0][5], xb0);

    conv_off_kernel<<<rowGrid, 128>>>(xb0, X, dw[1][0], dw[1][1],
                                      dw[1][2], dw[1][3], off_p, mask_p);
    deform_kernel<<<rowGrid, 256, DF_SMEM_BYTES>>>(xb0, X, dw[1][4], dw[1][5], xb1);

    conv_off_kernel<<<rowGrid, 128>>>(xb1, X, dw[2][0], dw[2][1],
                                      dw[2][2], dw[2][3], off_p, mask_p);
    deform_kernel<<<rowGrid, 256, DF_SMEM_BYTES>>>(xb1, X, dw[2][4], dw[2][5], xb0);

    conv_small_kernel<3><<<convGrid, 256>>>(xb0, X, conv_w, conv_b, xfin_p);

    pool_kernel<<<B_*3, 256>>>(xfin_p);
    ch_kernel<<<1, 64>>>(ch_w1, ch_b1, ch_w2, ch_b2);
    ddf_kernel<<<dim3(64, B_), 256>>>(sp_w, sp_b, out_main);
}

// round 4
// speedup vs baseline: 1.5051x; 1.0691x over previous
#include <cuda_runtime.h>
#include <math.h>

#define HW   16384
#define B_   4

// ---------------- scratch ------------------------------------------------------
__device__ float g_xbuf0[B_*64*HW];
__device__ float g_xbuf1[B_*64*HW];
__device__ float g_off  [B_*18*HW];
__device__ float g_mask [B_*9*HW];
__device__ float g_xfin [B_*3*HW];
__device__ float g_ch   [B_*16*27];
__device__ float g_pool [B_*3];

__device__ __forceinline__ float sigm(float v){ return 1.f/(1.f+__expf(-v)); }

// ---- packed fp32x2 helpers (bit-exact fp32 FMA, 2 lanes per issue slot) ------
typedef unsigned long long ull;
__device__ __forceinline__ ull dup2(float v){
    ull r; asm("mov.b64 %0, {%1, %1};" : "=l"(r) : "f"(v)); return r;
}
__device__ __forceinline__ void ffma2(ull &d, ull a, ull b){
    asm("fma.rn.f32x2 %0, %1, %2, %0;" : "+l"(d) : "l"(a), "l"(b));
}
__device__ __forceinline__ float2 unpk(ull v){
    float2 f; asm("mov.b64 {%0, %1}, %2;" : "=f"(f.x), "=f"(f.y) : "l"(v)); return f;
}

// ---------------- 1) ConvLSTM (h=c=0 => only 3 input channels, no f gate) -----
__global__ void lstm_kernel(const float* __restrict__ X, const float* __restrict__ w,
                            const float* __restrict__ bias,
                            float* __restrict__ hid, float* __restrict__ cell)
{
    int idx = blockIdx.x*256 + threadIdx.x;            // [b][k][y][x]
    int x = idx & 127, y = (idx >> 7) & 127, k = (idx >> 14) & 63, b = idx >> 20;
    float ai = bias[k], ao = bias[128+k], ag = bias[192+k];
    const float* Xb = X + b*3*HW;
    const float* wi = w + k*603;
    const float* wo = w + (128+k)*603;
    const float* wg = w + (192+k)*603;
    #pragma unroll
    for (int c = 0; c < 3; c++)
        #pragma unroll
        for (int dy = 0; dy < 3; dy++) {
            int yy = y + dy - 1;
            #pragma unroll
            for (int dx = 0; dx < 3; dx++) {
                int xx = x + dx - 1;
                float v = (yy >= 0 && yy < 128 && xx >= 0 && xx < 128)
                        ? Xb[c*HW + yy*128 + xx] : 0.f;
                int t = c*9 + dy*3 + dx;
                ai = fmaf(wi[t], v, ai);
                ao = fmaf(wo[t], v, ao);
                ag = fmaf(wg[t], v, ag);
            }
        }
    float cc = sigm(ai)*tanhf(ag);
    float hh = sigm(ao)*tanhf(cc);
    hid[idx]  = hh;
    cell[idx] = cc;
}

// ---------------- 2) offset/mask conv, f32x2 packed GEMM ----------------------
// Block = 256 threads, one full 128-px row. Thread tile: 4 outs (2 pairs) x 4 px.
__global__ __launch_bounds__(256) void conv_off_kernel(
    const float* __restrict__ xin, const float* __restrict__ lr,
    const float* __restrict__ w0, const float* __restrict__ b0,
    const float* __restrict__ w1, const float* __restrict__ b1,
    float* __restrict__ out0, float* __restrict__ out1)
{
    __shared__ float sTile[16*3*132];    // 16ch x 3 rows x 132 cols
    __shared__ float sW[144*32];         // transposed [tap][32 outs] (pad out>=27 with 0)

    int tid = threadIdx.x;
    int pg = tid & 31;                   // 4 px each -> 128 px
    int og = tid >> 5;                   // 8 groups x 4 outs = 32 outs
    int b = blockIdx.y, y = blockIdx.x;
    int y0 = y - 1;

    ull acc[2][4];                       // [out-pair][px]
    #pragma unroll
    for (int q = 0; q < 2; q++)
        #pragma unroll
        for (int p = 0; p < 4; p++) acc[q][p] = 0ull;

    for (int c0 = 0; c0 < 67; c0 += 16) {
        int cnt = (67 - c0) < 16 ? (67 - c0) : 16;
        // stage input rows (cols: gx = col-1, valid 0..127 -> col 1..128)
        for (int i = tid; i < cnt*396; i += 256) {
            int c = i / 396, rem = i - c*396;
            int r = rem / 132, col = rem - r*132;
            int gy = y0 + r, gx = col - 1;
            int cg = c0 + c;
            const float* src = (cg < 64) ? (xin + (b*64 + cg)*HW)
                                         : (lr  + (b*3 + (cg-64))*HW);
            sTile[i] = (gx >= 0 && gx < 128 && gy >= 0 && gy < 128)
                     ? src[gy*128 + gx] : 0.f;
        }
        // stage weights transposed
        int c09 = c0*9;
        for (int i = tid; i < cnt*288; i += 256) {
            int o = i & 31, tdx = i >> 5;
            float wv = 0.f;
            if (o < 18)      wv = w0[o*603 + c09 + tdx];
            else if (o < 27) wv = w1[(o-18)*603 + c09 + tdx];
            sW[tdx*32 + o] = wv;
        }
        __syncthreads();

        for (int c = 0; c < cnt; c++) {
            #pragma unroll
            for (int ky = 0; ky < 3; ky++) {
                const float* rb = sTile + c*396 + ky*132 + pg*4;
                float4 a4 = *(const float4*)rb;
                float2 a2 = *(const float2*)(rb + 4);
                ull vv[6];
                vv[0] = dup2(a4.x); vv[1] = dup2(a4.y); vv[2] = dup2(a4.z);
                vv[3] = dup2(a4.w); vv[4] = dup2(a2.x); vv[5] = dup2(a2.y);
                #pragma unroll
                for (int kx = 0; kx < 3; kx++) {
                    ulonglong2 w = *(const ulonglong2*)(sW + (c*9 + ky*3 + kx)*32 + og*4);
                    #pragma unroll
                    for (int p = 0; p < 4; p++) {
                        ffma2(acc[0][p], w.x, vv[kx + p]);
                        ffma2(acc[1][p], w.y, vv[kx + p]);
                    }
                }
            }
        }
        __syncthreads();
    }

    int pixb = y*128 + pg*4;
    #pragma unroll
    for (int wp = 0; wp < 2; wp++) {
        int o0 = og*4 + 2*wp;
        float2 a0 = unpk(acc[wp][0]), a1 = unpk(acc[wp][1]);
        float2 a2 = unpk(acc[wp][2]), a3 = unpk(acc[wp][3]);
        if (o0 < 18) {
            float bb = b0[o0];
            *(float4*)(out0 + (b*18 + o0)*HW + pixb) =
                make_float4(a0.x+bb, a1.x+bb, a2.x+bb, a3.x+bb);
        } else if (o0 < 27) {
            float bb = b1[o0-18];
            *(float4*)(out1 + (b*9 + (o0-18))*HW + pixb) =
                make_float4(2.f*sigm(a0.x+bb), 2.f*sigm(a1.x+bb),
                            2.f*sigm(a2.x+bb), 2.f*sigm(a3.x+bb));
        }
        int o1 = o0 + 1;
        if (o1 < 18) {
            float bb = b0[o1];
            *(float4*)(out0 + (b*18 + o1)*HW + pixb) =
                make_float4(a0.y+bb, a1.y+bb, a2.y+bb, a3.y+bb);
        } else if (o1 < 27) {
            float bb = b1[o1-18];
            *(float4*)(out1 + (b*9 + (o1-18))*HW + pixb) =
                make_float4(2.f*sigm(a0.y+bb), 2.f*sigm(a1.y+bb),
                            2.f*sigm(a2.y+bb), 2.f*sigm(a3.y+bb));
        }
    }
}

// ---------------- 2b) small direct conv (final 3-out fuse conv) ---------------
template<int COUT>
__global__ __launch_bounds__(256) void conv_small_kernel(
    const float* __restrict__ xin, const float* __restrict__ lr,
    const float* __restrict__ w0, const float* __restrict__ b0,
    float* __restrict__ out0)
{
    __shared__ float sT[16*10*34];
    __shared__ float sW[COUT*16*9];
    int tid = threadIdx.x;
    int tx = tid & 31, ty = tid >> 5;
    int b = blockIdx.z;
    int x = blockIdx.x*32 + tx, y = blockIdx.y*8 + ty;
    int gx0 = blockIdx.x*32 - 1, gy0 = blockIdx.y*8 - 1;

    float acc[COUT];
    #pragma unroll
    for (int o = 0; o < COUT; o++) acc[o] = 0.f;

    for (int c0 = 0; c0 < 67; c0 += 16) {
        int cnt = (67 - c0) < 16 ? (67 - c0) : 16;
        for (int i = tid; i < cnt*340; i += 256) {
            int c = i / 340, rem = i - c*340;
            int r = rem / 34, col = rem - r*34;
            int gy = gy0 + r, gx = gx0 + col;
            int cg = c0 + c;
            const float* src = (cg < 64) ? (xin + (b*64 + cg)*HW)
                                         : (lr  + (b*3 + (cg-64))*HW);
            sT[i] = (gy >= 0 && gy < 128 && gx >= 0 && gx < 128)
                  ? src[gy*128 + gx] : 0.f;
        }
        int wtot = COUT*cnt*9;
        for (int i = tid; i < wtot; i += 256) {
            int o = i / (cnt*9), rem = i - o*(cnt*9);
            sW[o*144 + rem] = w0[o*603 + c0*9 + rem];
        }
        __syncthreads();
        for (int c = 0; c < cnt; c++) {
            float win[9];
            #pragma unroll
            for (int r = 0; r < 3; r++)
                #pragma unroll
                for (int q = 0; q < 3; q++)
                    win[r*3+q] = sT[c*340 + (ty+r)*34 + (tx+q)];
            #pragma unroll
            for (int o = 0; o < COUT; o++) {
                #pragma unroll
                for (int t = 0; t < 9; t++)
                    acc[o] = fmaf(sW[o*144 + c*9 + t], win[t], acc[o]);
            }
        }
        __syncthreads();
    }
    int pix = y*128 + x;
    #pragma unroll
    for (int o = 0; o < COUT; o++)
        out0[(b*COUT + o)*HW + pix] = acc[o] + b0[o];
}

// ---------------- 3) deform: gather + 64x603 GEMM, f32x2, K-chunked -----------
// Block = 256 thr, one 128-px row. Thread tile: 8 outs (4 pairs) x 4 px.
// smem floats: sWt 1152*4 | sIdx 1152 | sV 67*132 | sWc 67*64
#define DF_SIDX  4608
#define DF_SV    (4608 + 1152)
#define DF_SWC   (DF_SV + 67*132)
#define DF_SMEM_BYTES ((DF_SWC + 67*64) * 4)

__global__ __launch_bounds__(256) void deform_kernel(
    const float* __restrict__ xin, const float* __restrict__ lr,
    const float* __restrict__ wmain, const float* __restrict__ bias,
    float* __restrict__ out)
{
    extern __shared__ float smem[];
    float4* sWt = (float4*)smem;                 // [k][128 px] corner weights
    int*    sIdx= (int*)(smem + DF_SIDX);
    float*  sV  = smem + DF_SV;                  // [j][px], stride 132
    float*  sWc = smem + DF_SWC;                 // [j][64 outs]

    int tid = threadIdx.x;
    int b = blockIdx.y, y = blockIdx.x;

    // ---- Phase A: bilinear meta (9 taps x 128 px) ----
    for (int e = tid; e < 1152; e += 256) {
        int p = e & 127, k = e >> 7;
        int pix = y*128 + p;
        float offy = g_off [(b*18 + 2*k    )*HW + pix];
        float offx = g_off [(b*18 + 2*k + 1)*HW + pix];
        float m    = g_mask[(b*9  + k      )*HW + pix];
        int ky = k / 3, kx = k - ky*3;
        float py = (float)(y + ky - 1) + offy;
        float px = (float)(p + kx - 1) + offx;
        float fy = floorf(py), fx = floorf(px);
        float wy = py - fy,    wx = px - fx;
        int iy = (int)fy, ix = (int)fx;
        bool vy0 = (iy   >= 0 && iy   <= 127);
        bool vy1 = (iy+1 >= 0 && iy+1 <= 127);
        bool vx0 = (ix   >= 0 && ix   <= 127);
        bool vx1 = (ix+1 >= 0 && ix+1 <= 127);
        float4 wv;
        wv.x = (1.f-wy)*(1.f-wx)*m * ((vy0 && vx0) ? 1.f : 0.f);
        wv.y = (1.f-wy)*wx      *m * ((vy0 && vx1) ? 1.f : 0.f);
        wv.z = wy*(1.f-wx)      *m * ((vy1 && vx0) ? 1.f : 0.f);
        wv.w = wy*wx            *m * ((vy1 && vx1) ? 1.f : 0.f);
        sWt[e] = wv;
        int iy0 = min(max(iy,   0), 127), iy1 = min(max(iy+1, 0), 127);
        int ix0 = min(max(ix,   0), 127), ix1 = min(max(ix+1, 0), 127);
        sIdx[e] = iy0 | (iy1 << 8) | (ix0 << 16) | (ix1 << 24);
    }
    __syncthreads();

    const float* xb = xin + b*64*HW;
    const float* lb = lr  + b*3*HW;
    int pg = tid & 31, og = tid >> 5;

    ull acc[4][4];
    #pragma unroll
    for (int q = 0; q < 4; q++)
        #pragma unroll
        for (int p = 0; p < 4; p++) acc[q][p] = 0ull;

    for (int c0 = 0; c0 < 603; c0 += 67) {
        // stage weight chunk transposed
        for (int i = tid; i < 67*64; i += 256) {
            int o = i & 63, j = i >> 6;
            sWc[j*64 + o] = wmain[o*603 + c0 + j];
        }
        // gather V chunk [67][128]
        for (int e = tid; e < 67*128; e += 256) {
            int p = e & 127, j = e >> 7;
            int kk = c0 + j;
            int c = kk / 9, k = kk - c*9;
            int mi = (k << 7) | p;
            float4 wt = sWt[mi];
            int pk = sIdx[mi];
            int iy0 =  pk        & 255, iy1 = (pk >> 8)  & 255;
            int ix0 = (pk >> 16) & 255, ix1 = (pk >> 24) & 255;
            const float* src = (c < 64) ? (xb + c*HW) : (lb + (c-64)*HW);
            float v = wt.x * __ldg(src + iy0*128 + ix0)
                    + wt.y * __ldg(src + iy0*128 + ix1)
                    + wt.z * __ldg(src + iy1*128 + ix0)
                    + wt.w * __ldg(src + iy1*128 + ix1);
            sV[j*132 + p] = v;
        }
        __syncthreads();

        const float* vp = sV + pg*4;
        const float* wp_ = sWc + og*8;
        #pragma unroll 4
        for (int j = 0; j < 67; j++) {
            ulonglong2 wA = *(const ulonglong2*)(wp_ + j*64);
            ulonglong2 wB = *(const ulonglong2*)(wp_ + j*64 + 4);
            float4 v = *(const float4*)(vp + j*132);
            ull v0 = dup2(v.x), v1 = dup2(v.y), v2 = dup2(v.z), v3 = dup2(v.w);
            ffma2(acc[0][0], wA.x, v0); ffma2(acc[0][1], wA.x, v1);
            ffma2(acc[0][2], wA.x, v2); ffma2(acc[0][3], wA.x, v3);
            ffma2(acc[1][0], wA.y, v0); ffma2(acc[1][1], wA.y, v1);
            ffma2(acc[1][2], wA.y, v2); ffma2(acc[1][3], wA.y, v3);
            ffma2(acc[2][0], wB.x, v0); ffma2(acc[2][1], wB.x, v1);
            ffma2(acc[2][2], wB.x, v2); ffma2(acc[2][3], wB.x, v3);
            ffma2(acc[3][0], wB.y, v0); ffma2(acc[3][1], wB.y, v1);
            ffma2(acc[3][2], wB.y, v2); ffma2(acc[3][3], wB.y, v3);
        }
        __syncthreads();
    }

    int pixb = y*128 + pg*4;
    #pragma unroll
    for (int wp = 0; wp < 4; wp++) {
        int o0 = og*8 + 2*wp;
        float2 a0 = unpk(acc[wp][0]), a1 = unpk(acc[wp][1]);
        float2 a2 = unpk(acc[wp][2]), a3 = unpk(acc[wp][3]);
        float bb0 = bias[o0], bb1 = bias[o0+1];
        *(float4*)(out + (b*64 + o0)*HW + pixb) =
            make_float4(a0.x+bb0, a1.x+bb0, a2.x+bb0, a3.x+bb0);
        *(float4*)(out + (b*64 + o0+1)*HW + pixb) =
            make_float4(a0.y+bb1, a1.y+bb1, a2.y+bb1, a3.y+bb1);
    }
}

// ---------------- 4) global average pool --------------------------------------
__global__ void pool_kernel(const float* __restrict__ xf)
{
    __shared__ float red[256];
    int bc = blockIdx.x, tid = threadIdx.x;
    float s = 0.f;
    const float* p = xf + bc*HW;
    for (int i = tid; i < HW; i += 256) s += p[i];
    red[tid] = s; __syncthreads();
    for (int st = 128; st > 0; st >>= 1) {
        if (tid < st) red[tid] += red[tid + st];
        __syncthreads();
    }
    if (tid == 0) g_pool[bc] = red[0] * (1.f/HW);
}

// ---------------- 5) channel-filter MLP ---------------------------------------
__global__ void ch_kernel(const float* __restrict__ ch_w1, const float* __restrict__ ch_b1,
                          const float* __restrict__ ch_w2, const float* __restrict__ ch_b2)
{
    int t = threadIdx.x;
    if (t >= 64) return;
    int b = t >> 4, s = t & 15;
    float h1[4];
    #pragma unroll
    for (int m = 0; m < 4; m++) {
        float a = ch_b1[s*4 + m];
        #pragma unroll
        for (int c = 0; c < 3; c++) a = fmaf(g_pool[b*3 + c], ch_w1[(s*4 + m)*3 + c], a);
        h1[m] = fmaxf(a, 0.f);
    }
    for (int k = 0; k < 27; k++) {
        float a = ch_b2[s*27 + k];
        #pragma unroll
        for (int m = 0; m < 4; m++) a = fmaf(h1[m], ch_w2[(s*27 + k)*4 + m], a);
        g_ch[(b*16 + s)*27 + k] = a;
    }
}

// ---------------- 6) DDF up ----------------------------------------------------
__global__ __launch_bounds__(256) void ddf_kernel(
    const float* __restrict__ spw, const float* __restrict__ spb,
    float* __restrict__ out)
{
    __shared__ float sSpw[144*28];
    __shared__ float sSpb[144];
    __shared__ float sCh[432];
    int b = blockIdx.y, tid = threadIdx.x;
    for (int i = tid; i < 144*28; i += 256) {
        int row = i / 28, col = i - row*28;
        sSpw[i] = (col < 27) ? spw[row*27 + col] : 0.f;
    }
    if (tid < 144) sSpb[tid] = spb[tid];
    for (int i = tid; i < 432; i += 256) sCh[i] = g_ch[b*432 + i];
    __syncthreads();

    int pix = blockIdx.x*256 + tid;
    int x = pix & 127, y = pix >> 7;
    const float* xb = g_xfin + b*3*HW;

    float win[28];
    win[27] = 0.f;
    #pragma unroll
    for (int c = 0; c < 3; c++)
        #pragma unroll
        for (int r = 0; r < 3; r++) {
            int yy = y + r - 1;
            #pragma unroll
            for (int q = 0; q < 3; q++) {
                int xx = x + q - 1;
                win[c*9 + r*3 + q] = (yy >= 0 && yy < 128 && xx >= 0 && xx < 128)
                                   ? xb[c*HW + yy*128 + xx] : 0.f;
            }
        }

    float* ob = out + b*3*(512*512);
    #pragma unroll 1
    for (int s = 0; s < 16; s++) {
        float a0 = 0.f, a1 = 0.f, a2 = 0.f;
        #pragma unroll
        for (int k = 0; k < 9; k++) {
            float spv = sSpb[s*9 + k];
            const float4* w4 = (const float4*)(sSpw + (s*9 + k)*28);
            #pragma unroll
            for (int j4 = 0; j4 < 7; j4++) {
                float4 w = w4[j4];
                spv = fmaf(w.x, win[j4*4 + 0], spv);
                spv = fmaf(w.y, win[j4*4 + 1], spv);
                spv = fmaf(w.z, win[j4*4 + 2], spv);
                spv = fmaf(w.w, win[j4*4 + 3], spv);
            }
            a0 = fmaf(win[k],      sCh[s*27 + k]      + spv, a0);
            a1 = fmaf(win[9 + k],  sCh[s*27 + 9 + k]  + spv, a1);
            a2 = fmaf(win[18 + k], sCh[s*27 + 18 + k] + spv, a2);
        }
        int oy = (y << 2) + (s >> 2), ox = (x << 2) + (s & 3);
        ob[0*262144 + oy*512 + ox] = fminf(fmaxf(a0, 0.f), 255.f);
        ob[1*262144 + oy*512 + ox] = fminf(fmaxf(a1, 0.f), 255.f);
        ob[2*262144 + oy*512 + ox] = fminf(fmaxf(a2, 0.f), 255.f);
    }
}

// ---------------- host orchestration ------------------------------------------
extern "C" void kernel_launch(void* const* d_in, const int* in_sizes, int n_in,
                              void* d_out, int out_size)
{
    const float* X      = (const float*)d_in[0];
    const float* lstm_w = (const float*)d_in[1];
    const float* lstm_b = (const float*)d_in[2];
    const float* dw[3][6];
    for (int i = 0; i < 3; i++)
        for (int j = 0; j < 6; j++)
            dw[i][j] = (const float*)d_in[3 + i*6 + j];   // ow, ob, mw, mb, w, b
    const float* conv_w = (const float*)d_in[21];
    const float* conv_b = (const float*)d_in[22];
    const float* sp_w   = (const float*)d_in[23];
    const float* sp_b   = (const float*)d_in[24];
    const float* ch_w1  = (const float*)d_in[25];
    const float* ch_b1  = (const float*)d_in[26];
    const float* ch_w2  = (const float*)d_in[27];
    const float* ch_b2  = (const float*)d_in[28];

    float* out_main = (float*)d_out;                     // [4,3,512,512]
    float* hid      = out_main + 4*3*512*512;            // [4,64,128,128]
    float* cell     = hid + 4*64*128*128;                // [4,64,128,128]

    void *pxb0, *pxb1, *poff, *pmask, *pxfin;
    cudaGetSymbolAddress(&pxb0, g_xbuf0);
    cudaGetSymbolAddress(&pxb1, g_xbuf1);
    cudaGetSymbolAddress(&poff,  g_off);
    cudaGetSymbolAddress(&pmask, g_mask);
    cudaGetSymbolAddress(&pxfin, g_xfin);
    float* xb0 = (float*)pxb0;
    float* xb1 = (float*)pxb1;
    float* off_p  = (float*)poff;
    float* mask_p = (float*)pmask;
    float* xfin_p = (float*)pxfin;

    cudaFuncSetAttribute(deform_kernel, cudaFuncAttributeMaxDynamicSharedMemorySize,
                         DF_SMEM_BYTES);

    dim3 rowGrid(128, B_);
    dim3 convGrid(4, 16, B_);

    lstm_kernel<<<16384, 256>>>(X, lstm_w, lstm_b, hid, cell);

    conv_off_kernel<<<rowGrid, 256>>>(hid, X, dw[0][0], dw[0][1],
                                      dw[0][2], dw[0][3], off_p, mask_p);
    deform_kernel<<<rowGrid, 256, DF_SMEM_BYTES>>>(hid, X, dw[0][4], dw[0][5], xb0);

    conv_off_kernel<<<rowGrid, 256>>>(xb0, X, dw[1][0], dw[1][1],
                                      dw[1][2], dw[1][3], off_p, mask_p);
    deform_kernel<<<rowGrid, 256, DF_SMEM_BYTES>>>(xb0, X, dw[1][4], dw[1][5], xb1);

    conv_off_kernel<<<rowGrid, 256>>>(xb1, X, dw[2][0], dw[2][1],
                                      dw[2][2], dw[2][3], off_p, mask_p);
    deform_kernel<<<rowGrid, 256, DF_SMEM_BYTES>>>(xb1, X, dw[2][4], dw[2][5], xb0);

    conv_small_kernel<3><<<convGrid, 256>>>(xb0, X, conv_w, conv_b, xfin_p);

    pool_kernel<<<B_*3, 256>>>(xfin_p);
    ch_kernel<<<1, 64>>>(ch_w1, ch_b1, ch_w2, ch_b2);
    ddf_kernel<<<dim3(64, B_), 256>>>(sp_w, sp_b, out_main);
}